// round 5
// baseline (speedup 1.0000x reference)
#include <cuda_runtime.h>
#include <cstdint>
#include <math.h>

#define H 8
#define C 32
#define NMAX 50000
#define EMAX 400000

__device__ float g_k_rinv[NMAX * H];
__device__ int   g_seg_begin[NMAX];
__device__ int   g_seg_end[NMAX];

// ---- L2 cache-policy helpers ----------------------------------------------
__device__ __forceinline__ unsigned long long pol_evict_last() {
    unsigned long long p;
    asm("createpolicy.fractional.L2::evict_last.b64 %0, 1.0;" : "=l"(p));
    return p;
}
__device__ __forceinline__ unsigned long long pol_evict_first() {
    unsigned long long p;
    asm("createpolicy.fractional.L2::evict_first.b64 %0, 1.0;" : "=l"(p));
    return p;
}
__device__ __forceinline__ float4 ldg_pol_f4(const float4* p, unsigned long long pol) {
    float4 r;
    asm("ld.global.nc.L2::cache_hint.v4.f32 {%0,%1,%2,%3}, [%4], %5;"
        : "=f"(r.x), "=f"(r.y), "=f"(r.z), "=f"(r.w)
        : "l"(p), "l"(pol));
    return r;
}
__device__ __forceinline__ int ldg_pol_s32(const int* p, unsigned long long pol) {
    int r;
    asm("ld.global.nc.L2::cache_hint.b32 %0, [%1], %2;" : "=r"(r) : "l"(p), "l"(pol));
    return r;
}
__device__ __forceinline__ float ldg_pol_f32(const float* p, unsigned long long pol) {
    float r;
    asm("ld.global.nc.L2::cache_hint.f32 %0, [%1], %2;" : "=f"(r) : "l"(p), "l"(pol));
    return r;
}
// ---------------------------------------------------------------------------

// Prepass: warp handles 4 rows (n*H+h). Lane layout: g=lane>>3 selects row,
// u=lane&7 selects float4 quarter. 512B contiguous per warp (nL=4 per LDG).
// Loads k with evict_last -> pre-warms L2 residency for main's gathers.
__global__ void gt_prep_kernel(const float* __restrict__ k, int N) {
    int gtid = blockIdx.x * blockDim.x + threadIdx.x;
    if (gtid < NMAX) { g_seg_begin[gtid] = 0; g_seg_end[gtid] = 0; }
    int warp = gtid >> 5;
    int lane = gtid & 31;
    int g = lane >> 3, u = lane & 7;
    int row = warp * 4 + g;
    if (row < N * H) {
        unsigned long long pl = pol_evict_last();
        float4 kv = ldg_pol_f4((const float4*)&k[row * C + u * 4], pl);
        float ss = kv.x*kv.x + kv.y*kv.y + kv.z*kv.z + kv.w*kv.w;
        ss += __shfl_xor_sync(0xffffffffu, ss, 4);
        ss += __shfl_xor_sync(0xffffffffu, ss, 2);
        ss += __shfl_xor_sync(0xffffffffu, ss, 1);
        float rinv = rsqrtf(ss * (1.0f / C) + 1e-6f);
        if (u == 0) g_k_rinv[row] = rinv;
    }
}

__global__ void gt_bounds_kernel(const int* __restrict__ dst, int E) {
    int i = blockIdx.x * blockDim.x + threadIdx.x;
    if (i >= E) return;
    int d = dst[i];
    if (i == 0 || dst[i - 1] != d) g_seg_begin[d] = i;
    if (i == E - 1 || dst[i + 1] != d) g_seg_end[d] = i + 1;
}

// Main: block per destination, warp per head.
// g=lane>>3 selects 1 of 4 edge slots, u=lane&7 selects float4 of the row.
// k/v/src/k_rinv loads: evict_last (pinned reused set, ~105MB < 126MB L2).
// e/q: evict_first (streamed once). out: __stcs.
// No online max: |s| bounded (~15), exp fits fp32; identical result.
__global__ __launch_bounds__(256) void gt_main_kernel(
    const float* __restrict__ q, const float* __restrict__ k,
    const float* __restrict__ v, const float* __restrict__ e,
    const float* __restrict__ wq, const float* __restrict__ wk,
    const int* __restrict__ src, float* __restrict__ out)
{
    int d    = blockIdx.x;
    int h    = threadIdx.x >> 5;
    int lane = threadIdx.x & 31;
    int g = lane >> 3, u = lane & 7;

    unsigned long long pl = pol_evict_last();
    unsigned long long pf = pol_evict_first();

    int b  = g_seg_begin[d];
    int en = g_seg_end[d];

    float4 wqc = *(const float4*)&wq[u * 4];
    float4 wkc = *(const float4*)&wk[u * 4];

    int rowq = (d * H + h) * C;
    float4 qv = ldg_pol_f4((const float4*)&q[rowq + u * 4], pf);
    float ss = qv.x*qv.x + qv.y*qv.y + qv.z*qv.z + qv.w*qv.w;
    ss += __shfl_xor_sync(0xffffffffu, ss, 4);
    ss += __shfl_xor_sync(0xffffffffu, ss, 2);
    ss += __shfl_xor_sync(0xffffffffu, ss, 1);
    float rq = rsqrtf(ss * (1.0f / C) + 1e-6f);
    float4 qn;
    qn.x = qv.x * rq * wqc.x; qn.y = qv.y * rq * wqc.y;
    qn.z = qv.z * rq * wqc.z; qn.w = qv.w * rq * wqc.w;

    const float qk_scale = 0.17677669529663687f;  // 1/sqrt(32)

    float  l   = 0.0f;
    float4 acc = make_float4(0.f, 0.f, 0.f, 0.f);

    for (int i = b; i < en; i += 4) {
        int ei   = i + g;
        bool act = (ei < en);
        int eidx = act ? ei : (en - 1);          // clamp: same line, no extra traffic
        int s    = ldg_pol_s32(&src[eidx], pl);
        float kr = ldg_pol_f32(&g_k_rinv[s * H + h], pl);
        int rowk = (s * H + h) * C + u * 4;
        float4 kv = ldg_pol_f4((const float4*)&k[rowk], pl);
        float4 vv = ldg_pol_f4((const float4*)&v[rowk], pl);
        float4 ev = ldg_pol_f4((const float4*)&e[(eidx * H + h) * C + u * 4], pf);

        float dot = qn.x * fmaf(kv.x * kr, wkc.x, ev.x)
                  + qn.y * fmaf(kv.y * kr, wkc.y, ev.y)
                  + qn.z * fmaf(kv.z * kr, wkc.z, ev.z)
                  + qn.w * fmaf(kv.w * kr, wkc.w, ev.w);
        dot += __shfl_xor_sync(0xffffffffu, dot, 4);
        dot += __shfl_xor_sync(0xffffffffu, dot, 2);
        dot += __shfl_xor_sync(0xffffffffu, dot, 1);

        float p = act ? __expf(dot * qk_scale) : 0.0f;
        l += p;
        acc.x = fmaf(p, vv.x + ev.x, acc.x);
        acc.y = fmaf(p, vv.y + ev.y, acc.y);
        acc.z = fmaf(p, vv.z + ev.z, acc.z);
        acc.w = fmaf(p, vv.w + ev.w, acc.w);
    }

    // Reduce the 4 edge-slot partials (lanes differing in bits 3,4).
    l += __shfl_xor_sync(0xffffffffu, l, 8);
    l += __shfl_xor_sync(0xffffffffu, l, 16);
    acc.x += __shfl_xor_sync(0xffffffffu, acc.x, 8);
    acc.x += __shfl_xor_sync(0xffffffffu, acc.x, 16);
    acc.y += __shfl_xor_sync(0xffffffffu, acc.y, 8);
    acc.y += __shfl_xor_sync(0xffffffffu, acc.y, 16);
    acc.z += __shfl_xor_sync(0xffffffffu, acc.z, 8);
    acc.z += __shfl_xor_sync(0xffffffffu, acc.z, 16);
    acc.w += __shfl_xor_sync(0xffffffffu, acc.w, 8);
    acc.w += __shfl_xor_sync(0xffffffffu, acc.w, 16);

    if (g == 0) {
        float inv = (l > 0.0f) ? (1.0f / fmaxf(l, 1e-30f)) : 0.0f;
        float4 o;
        o.x = acc.x * inv; o.y = acc.y * inv;
        o.z = acc.z * inv; o.w = acc.w * inv;
        __stcs((float4*)&out[rowq + u * 4], o);
    }
}

extern "C" void kernel_launch(void* const* d_in, const int* in_sizes, int n_in,
                              void* d_out, int out_size) {
    const float* q   = (const float*)d_in[0];
    const float* k   = (const float*)d_in[1];
    const float* v   = (const float*)d_in[2];
    const float* e   = (const float*)d_in[3];
    const float* wq  = (const float*)d_in[4];
    const float* wk  = (const float*)d_in[5];
    const int*   src = (const int*)d_in[6];
    const int*   dst = (const int*)d_in[7];
    float* out = (float*)d_out;

    int N  = in_sizes[0] / (H * C);
    int NH = N * H;
    int E  = in_sizes[6];

    int prep_threads = ((NH + 3) / 4) * 32;   // warp per 4 rows
    if (prep_threads < NMAX) prep_threads = NMAX;
    gt_prep_kernel<<<(prep_threads + 255) / 256, 256>>>(k, N);
    gt_bounds_kernel<<<(E + 255) / 256, 256>>>(dst, E);
    gt_main_kernel<<<N, 256>>>(q, k, v, e, wq, wk, src, out);
}

// round 7
// speedup vs baseline: 1.6133x; 1.6133x over previous
#include <cuda_runtime.h>
#include <cuda_fp16.h>
#include <cstdint>
#include <math.h>

#define H 8
#define C 32
#define NMAX 50000
#define EMAX 400000

// Packed normalized-K / V in fp16: g_kv[(n*H+h)*C + c] = half2(kn_c, v_c),
// kn_c = k_c * rinv * wk_c. One 128B line per (n,h) row -> single-line gather.
__device__ __half2 g_kv[NMAX * H * C];
__device__ int     g_seg_begin[NMAX];
__device__ int     g_seg_end[NMAX];

// Prepass: warp handles 4 rows (n*H+h). g=lane>>3 selects row, u=lane&7 the
// float4 quarter. Computes RMSNorm of k, packs half2(kn, v).
__global__ void gt_prep_kernel(const float* __restrict__ k,
                               const float* __restrict__ v,
                               const float* __restrict__ wk, int NH) {
    int gtid = blockIdx.x * blockDim.x + threadIdx.x;
    if (gtid < NMAX) { g_seg_begin[gtid] = 0; g_seg_end[gtid] = 0; }
    int warp = gtid >> 5;
    int lane = gtid & 31;
    int g = lane >> 3, u = lane & 7;
    int row = warp * 4 + g;
    if (row < NH) {
        float4 kv = __ldg((const float4*)&k[row * C + u * 4]);
        float ss = kv.x*kv.x + kv.y*kv.y + kv.z*kv.z + kv.w*kv.w;
        ss += __shfl_xor_sync(0xffffffffu, ss, 4);
        ss += __shfl_xor_sync(0xffffffffu, ss, 2);
        ss += __shfl_xor_sync(0xffffffffu, ss, 1);
        float rinv = rsqrtf(ss * (1.0f / C) + 1e-6f);
        float4 vv  = __ldg((const float4*)&v[row * C + u * 4]);
        float4 wkc = __ldg((const float4*)&wk[u * 4]);
        __half2 h0 = __floats2half2_rn(kv.x * rinv * wkc.x, vv.x);
        __half2 h1 = __floats2half2_rn(kv.y * rinv * wkc.y, vv.y);
        __half2 h2 = __floats2half2_rn(kv.z * rinv * wkc.z, vv.z);
        __half2 h3 = __floats2half2_rn(kv.w * rinv * wkc.w, vv.w);
        uint4 pack;
        pack.x = *(unsigned int*)&h0;
        pack.y = *(unsigned int*)&h1;
        pack.z = *(unsigned int*)&h2;
        pack.w = *(unsigned int*)&h3;
        *(uint4*)&g_kv[row * C + u * 4] = pack;
    }
}

__global__ void gt_bounds_kernel(const int* __restrict__ dst, int E) {
    int i = blockIdx.x * blockDim.x + threadIdx.x;
    if (i >= E) return;
    int d = dst[i];
    if (i == 0 || dst[i - 1] != d) g_seg_begin[d] = i;
    if (i == E - 1 || dst[i + 1] != d) g_seg_end[d] = i + 1;
}

// Main: block per destination, warp per head.
// g=lane>>3 picks 1 of 4 edge slots, u=lane&7 picks 4 channels (float4/uint4).
// Per edge-head: ONE 128B gather (packed kn/v) + streamed e row.
// No online max (|s| bounded; exp fits fp32 -> identical result).
__global__ __launch_bounds__(256) void gt_main_kernel(
    const float* __restrict__ q, const float* __restrict__ e,
    const float* __restrict__ wq, const int* __restrict__ src,
    float* __restrict__ out)
{
    int d    = blockIdx.x;
    int h    = threadIdx.x >> 5;
    int lane = threadIdx.x & 31;
    int g = lane >> 3, u = lane & 7;

    int b  = g_seg_begin[d];
    int en = g_seg_end[d];

    float4 wqc = *(const float4*)&wq[u * 4];

    int rowq = (d * H + h) * C;
    float4 qv = __ldcs((const float4*)&q[rowq + u * 4]);
    float ss = qv.x*qv.x + qv.y*qv.y + qv.z*qv.z + qv.w*qv.w;
    ss += __shfl_xor_sync(0xffffffffu, ss, 4);
    ss += __shfl_xor_sync(0xffffffffu, ss, 2);
    ss += __shfl_xor_sync(0xffffffffu, ss, 1);
    const float qk_scale = 0.17677669529663687f;  // 1/sqrt(32)
    float rq = rsqrtf(ss * (1.0f / C) + 1e-6f) * qk_scale;
    float4 qn;  // includes wq and qk_scale
    qn.x = qv.x * rq * wqc.x; qn.y = qv.y * rq * wqc.y;
    qn.z = qv.z * rq * wqc.z; qn.w = qv.w * rq * wqc.w;

    float  l   = 0.0f;
    float4 acc = make_float4(0.f, 0.f, 0.f, 0.f);

    for (int i = b; i < en; i += 4) {
        int ei   = i + g;
        bool act = (ei < en);
        int eidx = act ? ei : (en - 1);          // clamp: same line, no extra traffic
        int s    = __ldg(&src[eidx]);

        uint4 pk = *(const uint4*)&g_kv[(s * H + h) * C + u * 4];
        float4 ev = __ldcs((const float4*)&e[(eidx * H + h) * C + u * 4]);

        float2 c0 = __half22float2(*(__half2*)&pk.x);  // (kn, v) ch 4u+0
        float2 c1 = __half22float2(*(__half2*)&pk.y);
        float2 c2 = __half22float2(*(__half2*)&pk.z);
        float2 c3 = __half22float2(*(__half2*)&pk.w);

        float dot = qn.x * (c0.x + ev.x)
                  + qn.y * (c1.x + ev.y)
                  + qn.z * (c2.x + ev.z)
                  + qn.w * (c3.x + ev.w);
        dot += __shfl_xor_sync(0xffffffffu, dot, 4);
        dot += __shfl_xor_sync(0xffffffffu, dot, 2);
        dot += __shfl_xor_sync(0xffffffffu, dot, 1);

        float p = act ? __expf(dot) : 0.0f;
        l += p;
        acc.x = fmaf(p, c0.y + ev.x, acc.x);
        acc.y = fmaf(p, c1.y + ev.y, acc.y);
        acc.z = fmaf(p, c2.y + ev.z, acc.z);
        acc.w = fmaf(p, c3.y + ev.w, acc.w);
    }

    // Reduce the 4 edge-slot partials (lanes differing in bits 3,4).
    l += __shfl_xor_sync(0xffffffffu, l, 8);
    l += __shfl_xor_sync(0xffffffffu, l, 16);
    acc.x += __shfl_xor_sync(0xffffffffu, acc.x, 8);
    acc.x += __shfl_xor_sync(0xffffffffu, acc.x, 16);
    acc.y += __shfl_xor_sync(0xffffffffu, acc.y, 8);
    acc.y += __shfl_xor_sync(0xffffffffu, acc.y, 16);
    acc.z += __shfl_xor_sync(0xffffffffu, acc.z, 8);
    acc.z += __shfl_xor_sync(0xffffffffu, acc.z, 16);
    acc.w += __shfl_xor_sync(0xffffffffu, acc.w, 8);
    acc.w += __shfl_xor_sync(0xffffffffu, acc.w, 16);

    if (g == 0) {
        float inv = (l > 0.0f) ? (1.0f / fmaxf(l, 1e-30f)) : 0.0f;
        float4 o;
        o.x = acc.x * inv; o.y = acc.y * inv;
        o.z = acc.z * inv; o.w = acc.w * inv;
        __stcs((float4*)&out[rowq + u * 4], o);
    }
}

extern "C" void kernel_launch(void* const* d_in, const int* in_sizes, int n_in,
                              void* d_out, int out_size) {
    const float* q   = (const float*)d_in[0];
    const float* k   = (const float*)d_in[1];
    const float* v   = (const float*)d_in[2];
    const float* e   = (const float*)d_in[3];
    const float* wq  = (const float*)d_in[4];
    const float* wk  = (const float*)d_in[5];
    const int*   src = (const int*)d_in[6];
    const int*   dst = (const int*)d_in[7];
    float* out = (float*)d_out;

    int N  = in_sizes[0] / (H * C);
    int NH = N * H;
    int E  = in_sizes[6];

    int prep_threads = ((NH + 3) / 4) * 32;   // warp per 4 rows
    if (prep_threads < NMAX) prep_threads = NMAX;
    gt_prep_kernel<<<(prep_threads + 255) / 256, 256>>>(k, v, wk, NH);
    gt_bounds_kernel<<<(E + 255) / 256, 256>>>(dst, E);
    gt_main_kernel<<<N, 256>>>(q, e, wq, src, out);
}

// round 8
// speedup vs baseline: 1.6356x; 1.0138x over previous
#include <cuda_runtime.h>
#include <cuda_fp16.h>
#include <cstdint>
#include <math.h>

#define H 8
#define C 32
#define NMAX 50000
#define EMAX 400000

// Packed normalized-K / V in fp16: g_kv[(n*H+h)*C + c] = half2(kn_c, v_c),
// kn_c = k_c * rinv * wk_c. One 128B line per (n,h) row -> single-line gather.
// Kept evict-NORMAL in L2 (the reused hot set, ~51MB < 126MB L2).
__device__ __half2 g_kv[NMAX * H * C];
__device__ int     g_seg_begin[NMAX];
__device__ int     g_seg_end[NMAX];

// ---- L2 evict_first policy for single-use streams --------------------------
__device__ __forceinline__ unsigned long long pol_evict_first() {
    unsigned long long p;
    asm("createpolicy.fractional.L2::evict_first.b64 %0, 1.0;" : "=l"(p));
    return p;
}
__device__ __forceinline__ float4 ldg_ef_f4(const float4* p, unsigned long long pol) {
    float4 r;
    asm("ld.global.nc.L2::cache_hint.v4.f32 {%0,%1,%2,%3}, [%4], %5;"
        : "=f"(r.x), "=f"(r.y), "=f"(r.z), "=f"(r.w)
        : "l"(p), "l"(pol));
    return r;
}
// ---------------------------------------------------------------------------

// Prepass: warp handles 4 rows (n*H+h). g=lane>>3 selects row, u=lane&7 the
// float4 quarter. Computes RMSNorm of k, packs half2(kn, v).
// k/v loads are evict_first streams; g_kv stores are normal (pre-warm L2).
__global__ void gt_prep_kernel(const float* __restrict__ k,
                               const float* __restrict__ v,
                               const float* __restrict__ wk, int NH) {
    int gtid = blockIdx.x * blockDim.x + threadIdx.x;
    if (gtid < NMAX) { g_seg_begin[gtid] = 0; g_seg_end[gtid] = 0; }
    int warp = gtid >> 5;
    int lane = gtid & 31;
    int g = lane >> 3, u = lane & 7;
    int row = warp * 4 + g;
    if (row < NH) {
        unsigned long long pf = pol_evict_first();
        float4 kv = ldg_ef_f4((const float4*)&k[row * C + u * 4], pf);
        float ss = kv.x*kv.x + kv.y*kv.y + kv.z*kv.z + kv.w*kv.w;
        ss += __shfl_xor_sync(0xffffffffu, ss, 4);
        ss += __shfl_xor_sync(0xffffffffu, ss, 2);
        ss += __shfl_xor_sync(0xffffffffu, ss, 1);
        float rinv = rsqrtf(ss * (1.0f / C) + 1e-6f);
        float4 vv  = ldg_ef_f4((const float4*)&v[row * C + u * 4], pf);
        float4 wkc = __ldg((const float4*)&wk[u * 4]);
        __half2 h0 = __floats2half2_rn(kv.x * rinv * wkc.x, vv.x);
        __half2 h1 = __floats2half2_rn(kv.y * rinv * wkc.y, vv.y);
        __half2 h2 = __floats2half2_rn(kv.z * rinv * wkc.z, vv.z);
        __half2 h3 = __floats2half2_rn(kv.w * rinv * wkc.w, vv.w);
        uint4 pack;
        pack.x = *(unsigned int*)&h0;
        pack.y = *(unsigned int*)&h1;
        pack.z = *(unsigned int*)&h2;
        pack.w = *(unsigned int*)&h3;
        *(uint4*)&g_kv[row * C + u * 4] = pack;
    }
}

__global__ void gt_bounds_kernel(const int* __restrict__ dst, int E) {
    int i = blockIdx.x * blockDim.x + threadIdx.x;
    if (i >= E) return;
    int d = dst[i];
    if (i == 0 || dst[i - 1] != d) g_seg_begin[d] = i;
    if (i == E - 1 || dst[i + 1] != d) g_seg_end[d] = i + 1;
}

// Main: block per destination, warp per head.
// g=lane>>3 picks 1 of 4 edge slots, u=lane&7 picks 4 channels (float4/uint4).
// Per edge-head: ONE 128B gather (packed kn/v, evict-normal) + evict_first e row.
// No online max (|s| bounded; exp fits fp32 -> identical result).
__global__ __launch_bounds__(256) void gt_main_kernel(
    const float* __restrict__ q, const float* __restrict__ e,
    const float* __restrict__ wq, const int* __restrict__ src,
    float* __restrict__ out)
{
    int d    = blockIdx.x;
    int h    = threadIdx.x >> 5;
    int lane = threadIdx.x & 31;
    int g = lane >> 3, u = lane & 7;

    unsigned long long pf = pol_evict_first();

    int b  = g_seg_begin[d];
    int en = g_seg_end[d];

    float4 wqc = *(const float4*)&wq[u * 4];

    int rowq = (d * H + h) * C;
    float4 qv = ldg_ef_f4((const float4*)&q[rowq + u * 4], pf);
    float ss = qv.x*qv.x + qv.y*qv.y + qv.z*qv.z + qv.w*qv.w;
    ss += __shfl_xor_sync(0xffffffffu, ss, 4);
    ss += __shfl_xor_sync(0xffffffffu, ss, 2);
    ss += __shfl_xor_sync(0xffffffffu, ss, 1);
    const float qk_scale = 0.17677669529663687f;  // 1/sqrt(32)
    float rq = rsqrtf(ss * (1.0f / C) + 1e-6f) * qk_scale;
    float4 qn;  // includes wq and qk_scale
    qn.x = qv.x * rq * wqc.x; qn.y = qv.y * rq * wqc.y;
    qn.z = qv.z * rq * wqc.z; qn.w = qv.w * rq * wqc.w;

    float  l   = 0.0f;
    float4 acc = make_float4(0.f, 0.f, 0.f, 0.f);

    for (int i = b; i < en; i += 4) {
        int ei   = i + g;
        bool act = (ei < en);
        int eidx = act ? ei : (en - 1);          // clamp: same line, no extra traffic
        int s    = __ldg(&src[eidx]);

        uint4 pk = *(const uint4*)&g_kv[(s * H + h) * C + u * 4];   // evict-normal
        float4 ev = ldg_ef_f4((const float4*)&e[(eidx * H + h) * C + u * 4], pf);

        float2 c0 = __half22float2(*(__half2*)&pk.x);  // (kn, v) ch 4u+0
        float2 c1 = __half22float2(*(__half2*)&pk.y);
        float2 c2 = __half22float2(*(__half2*)&pk.z);
        float2 c3 = __half22float2(*(__half2*)&pk.w);

        float dot = qn.x * (c0.x + ev.x)
                  + qn.y * (c1.x + ev.y)
                  + qn.z * (c2.x + ev.z)
                  + qn.w * (c3.x + ev.w);
        dot += __shfl_xor_sync(0xffffffffu, dot, 4);
        dot += __shfl_xor_sync(0xffffffffu, dot, 2);
        dot += __shfl_xor_sync(0xffffffffu, dot, 1);

        float p = act ? __expf(dot) : 0.0f;
        l += p;
        acc.x = fmaf(p, c0.y + ev.x, acc.x);
        acc.y = fmaf(p, c1.y + ev.y, acc.y);
        acc.z = fmaf(p, c2.y + ev.z, acc.z);
        acc.w = fmaf(p, c3.y + ev.w, acc.w);
    }

    // Reduce the 4 edge-slot partials (lanes differing in bits 3,4).
    l += __shfl_xor_sync(0xffffffffu, l, 8);
    l += __shfl_xor_sync(0xffffffffu, l, 16);
    acc.x += __shfl_xor_sync(0xffffffffu, acc.x, 8);
    acc.x += __shfl_xor_sync(0xffffffffu, acc.x, 16);
    acc.y += __shfl_xor_sync(0xffffffffu, acc.y, 8);
    acc.y += __shfl_xor_sync(0xffffffffu, acc.y, 16);
    acc.z += __shfl_xor_sync(0xffffffffu, acc.z, 8);
    acc.z += __shfl_xor_sync(0xffffffffu, acc.z, 16);
    acc.w += __shfl_xor_sync(0xffffffffu, acc.w, 8);
    acc.w += __shfl_xor_sync(0xffffffffu, acc.w, 16);

    if (g == 0) {
        float inv = (l > 0.0f) ? (1.0f / fmaxf(l, 1e-30f)) : 0.0f;
        float4 o;
        o.x = acc.x * inv; o.y = acc.y * inv;
        o.z = acc.z * inv; o.w = acc.w * inv;
        __stcs((float4*)&out[rowq + u * 4], o);
    }
}

extern "C" void kernel_launch(void* const* d_in, const int* in_sizes, int n_in,
                              void* d_out, int out_size) {
    const float* q   = (const float*)d_in[0];
    const float* k   = (const float*)d_in[1];
    const float* v   = (const float*)d_in[2];
    const float* e   = (const float*)d_in[3];
    const float* wq  = (const float*)d_in[4];
    const float* wk  = (const float*)d_in[5];
    const int*   src = (const int*)d_in[6];
    const int*   dst = (const int*)d_in[7];
    float* out = (float*)d_out;

    int N  = in_sizes[0] / (H * C);
    int NH = N * H;
    int E  = in_sizes[6];

    int prep_threads = ((NH + 3) / 4) * 32;   // warp per 4 rows
    if (prep_threads < NMAX) prep_threads = NMAX;
    gt_prep_kernel<<<(prep_threads + 255) / 256, 256>>>(k, v, wk, NH);
    gt_bounds_kernel<<<(E + 255) / 256, 256>>>(dst, E);
    gt_main_kernel<<<N, 256>>>(q, e, wq, src, out);
}